// round 1
// baseline (speedup 1.0000x reference)
#include <cuda_runtime.h>
#include <cuda_bf16.h>
#include <cstdint>

#define TAGS 2048
#define NCTA 128
#define ROWS 16          // rows per CTA; NCTA*ROWS == TAGS
#define NTHR 256
#define NEGV -10000.0f

// ---------------- persistent device state (static globals, no allocation) ----
__device__ __nv_bfloat16 g_E[(size_t)TAGS * TAGS];   // exp(trans - rowmax), 8 MB
__device__ float g_rowmax[TAGS];
__device__ float g_fv[2][TAGS];                      // double-buffered forward var
__device__ float g_shift[2];                         // per-step safe shift
__device__ unsigned g_bar;                           // grid barrier counter

// ---------------- precompute: E = exp(trans - rowmax) in bf16 ---------------
__global__ void prep_kernel(const float* __restrict__ trans) {
    __shared__ float red[32];
    int i = blockIdx.x;
    int t = threadIdx.x;
    const float* row = trans + (size_t)i * TAGS;
    float m = -3.4e38f;
    for (int j = t; j < TAGS; j += NTHR) m = fmaxf(m, row[j]);
    #pragma unroll
    for (int o = 16; o; o >>= 1) m = fmaxf(m, __shfl_xor_sync(~0u, m, o));
    if ((t & 31) == 0) red[t >> 5] = m;
    __syncthreads();
    if (t < 32) {
        float v = (t < NTHR / 32) ? red[t] : -3.4e38f;
        #pragma unroll
        for (int o = 16; o; o >>= 1) v = fmaxf(v, __shfl_xor_sync(~0u, v, o));
        if (t == 0) red[0] = v;
    }
    __syncthreads();
    m = red[0];
    if (t == 0) g_rowmax[i] = m;
    for (int j = t; j < TAGS; j += NTHR)
        g_E[(size_t)i * TAGS + j] = __float2bfloat16(__expf(row[j] - m));
}

// ---------------- per-call state reset (graph-replay safe) ------------------
__global__ void init_kernel() {
    int j = blockIdx.x * blockDim.x + threadIdx.x;
    if (j < TAGS) g_fv[0][j] = (j == 0) ? 0.0f : NEGV;
    if (j == 0) { g_bar = 0u; g_shift[0] = 0.0f; g_shift[1] = 0.0f; }
}

__device__ __forceinline__ float2 bf2_to_f2(unsigned u) {
    float2 r;
    r.x = __uint_as_float(u << 16);
    r.y = __uint_as_float(u & 0xffff0000u);
    return r;
}

// ---------------- persistent main kernel ------------------------------------
extern "C" __global__ void __launch_bounds__(NTHR, 1)
crf_main(const float* __restrict__ h, const float* __restrict__ trans,
         float* __restrict__ out, int S) {
    extern __shared__ char smem[];
    uint4* Es   = (uint4*)smem;                                    // 16x2048 bf16 = 64 KB
    float* sp   = (float*)(smem + (size_t)ROWS * TAGS * 2);        // p[2048], 8 KB
    float* part = (float*)(smem + (size_t)ROWS * TAGS * 2 + TAGS * 4); // 16x8 partials

    const int b = blockIdx.x, t = threadIdx.x;
    const int lane = t & 31, wid = t >> 5;
    const int row0 = b * ROWS;
    const unsigned nb = gridDim.x;

    // load this CTA's E tile into shared memory (stays resident for all steps)
    {
        const uint4* Eg = (const uint4*)(g_E + (size_t)row0 * TAGS);
        for (int k = t; k < ROWS * TAGS / 8; k += NTHR) Es[k] = Eg[k];
    }
    float myrmax = 0.f;
    if (t < ROWS) myrmax = g_rowmax[row0 + t];
    __syncthreads();

    for (int s = 0; s < S; s++) {
        const float shift = *((volatile float*)&g_shift[s & 1]);
        const float* fvr = g_fv[s & 1];

        // p[j] = exp(fv[j] - shift)   (L1-bypassing loads: fv written by other SMs)
        #pragma unroll
        for (int k = 0; k < TAGS / NTHR; k++) {
            int j = t + NTHR * k;
            sp[j] = __expf(__ldcg(fvr + j) - shift);
        }
        float emit = 0.f;
        if (t < ROWS) emit = __ldg(h + (size_t)s * TAGS + row0 + t);
        __syncthreads();

        // GEMV: thread t covers cols [8t, 8t+8) for all 16 rows
        const float4 pa = *((const float4*)(sp + 8 * t));
        const float4 pb = *((const float4*)(sp + 8 * t + 4));
        float acc[ROWS];
        #pragma unroll
        for (int r = 0; r < ROWS; r++) {
            uint4 e = Es[r * (TAGS / 8) + t];
            float2 e0 = bf2_to_f2(e.x), e1 = bf2_to_f2(e.y);
            float2 e2 = bf2_to_f2(e.z), e3 = bf2_to_f2(e.w);
            float a;
            a  = pa.x * e0.x;  a += pa.y * e0.y;
            a += pa.z * e1.x;  a += pa.w * e1.y;
            a += pb.x * e2.x;  a += pb.y * e2.y;
            a += pb.z * e3.x;  a += pb.w * e3.y;
            acc[r] = a;
        }
        #pragma unroll
        for (int r = 0; r < ROWS; r++) {
            float a = acc[r];
            #pragma unroll
            for (int o = 16; o; o >>= 1) a += __shfl_xor_sync(~0u, a, o);
            if (lane == 0) part[r * 8 + wid] = a;
        }
        __syncthreads();

        if (t < ROWS) {
            float ssum = part[t * 8 + 0];
            #pragma unroll
            for (int w = 1; w < 8; w++) ssum += part[t * 8 + w];
            float nf = __logf(ssum) + shift + myrmax + emit;
            g_fv[(s + 1) & 1][row0 + t] = nf;
            if (row0 + t == 2) g_shift[(s + 1) & 1] = nf;   // shift for next step
        }
        __threadfence();
        __syncthreads();
        // lightweight grid barrier (all NCTA CTAs are co-resident: 128 <= 148 SMs)
        if (t == 0) {
            atomicAdd(&g_bar, 1u);
            const unsigned target = (unsigned)(s + 1) * nb;
            while (*((volatile unsigned*)&g_bar) < target) { }
            __threadfence();
        }
        __syncthreads();
    }

    // final: logsumexp(fv + trans[END=1, :]) on CTA 0
    if (b == 0) {
        const float* fvf = g_fv[S & 1];
        const float* trow = trans + TAGS;   // row END_IDX = 1
        float lm = -3.4e38f;
        #pragma unroll
        for (int k = 0; k < TAGS / NTHR; k++) {
            int j = t + NTHR * k;
            float v = __ldcg(fvf + j) + __ldg(trow + j);
            sp[j] = v;
            lm = fmaxf(lm, v);
        }
        #pragma unroll
        for (int o = 16; o; o >>= 1) lm = fmaxf(lm, __shfl_xor_sync(~0u, lm, o));
        if (lane == 0) part[wid] = lm;
        __syncthreads();
        float M = part[0];
        #pragma unroll
        for (int w = 1; w < 8; w++) M = fmaxf(M, part[w]);
        float sum = 0.f;
        #pragma unroll
        for (int k = 0; k < TAGS / NTHR; k++)
            sum += __expf(sp[t + NTHR * k] - M);
        #pragma unroll
        for (int o = 16; o; o >>= 1) sum += __shfl_xor_sync(~0u, sum, o);
        __syncthreads();
        if (lane == 0) part[wid] = sum;
        __syncthreads();
        if (t == 0) {
            float tot = 0.f;
            #pragma unroll
            for (int w = 0; w < 8; w++) tot += part[w];
            out[0] = __logf(tot) + M;
        }
    }
}

// ---------------- launch ----------------------------------------------------
extern "C" void kernel_launch(void* const* d_in, const int* in_sizes, int n_in,
                              void* d_out, int out_size) {
    const float* h     = (const float*)d_in[0];
    const float* trans = (const float*)d_in[1];
    float* out = (float*)d_out;
    const int S = in_sizes[0] / TAGS;

    const size_t smem = (size_t)ROWS * TAGS * 2 + (size_t)TAGS * 4 + ROWS * 8 * 4;
    cudaFuncSetAttribute(crf_main, cudaFuncAttributeMaxDynamicSharedMemorySize, (int)smem);

    init_kernel<<<(TAGS + 255) / 256, 256>>>();
    prep_kernel<<<TAGS, NTHR>>>(trans);
    crf_main<<<NCTA, NTHR, smem>>>(h, trans, out, S);
}

// round 3
// speedup vs baseline: 1.4362x; 1.4362x over previous
#include <cuda_runtime.h>
#include <cstdint>

#define TAGS 2048
#define NCTA 128
#define ROWS 16          // NCTA*ROWS == TAGS
#define NTHR 256
#define NEGV -10000.0f

// ---------------- persistent device state ----------------
__device__ float    g_fv[2][TAGS];       // double-buffered forward variable
__device__ unsigned g_bar;               // grid barrier counter (R1-proven)

__global__ void init_kernel() {
    int j = blockIdx.x * blockDim.x + threadIdx.x;
    if (j < TAGS) g_fv[0][j] = (j == 0) ? 0.0f : NEGV;
    if (j == 0) g_bar = 0u;
}

// ---------------- persistent main kernel ------------------------------------
extern "C" __global__ void __launch_bounds__(NTHR, 1)
crf_main(const float* __restrict__ h, const float* __restrict__ trans,
         float* __restrict__ out, int S) {
    __shared__ float2 part2[8 * NTHR];   // 16 KB reduction scratch
    __shared__ float  s_rmax[ROWS];
    __shared__ float  s_shift;

    const int b = blockIdx.x, t = threadIdx.x;
    const int lane = t & 31, w = t >> 5;
    const int row0 = b * ROWS;
    const int c0 = 8 * t;                // this thread's 8 columns
    const unsigned nb = gridDim.x;

    // ---- prologue: build E = exp(trans - rowmax) in REGISTERS (f32) --------
    float E[ROWS][8];
    {
        float lm[ROWS];
        #pragma unroll
        for (int r = 0; r < ROWS; r++) {
            const float4* tp = (const float4*)(trans + (size_t)(row0 + r) * TAGS + c0);
            float4 a = __ldg(tp), bb = __ldg(tp + 1);
            E[r][0] = a.x;  E[r][1] = a.y;  E[r][2] = a.z;  E[r][3] = a.w;
            E[r][4] = bb.x; E[r][5] = bb.y; E[r][6] = bb.z; E[r][7] = bb.w;
            lm[r] = fmaxf(fmaxf(fmaxf(a.x, a.y), fmaxf(a.z, a.w)),
                          fmaxf(fmaxf(bb.x, bb.y), fmaxf(bb.z, bb.w)));
        }
        #pragma unroll
        for (int pr = 0; pr < 8; pr++)
            part2[pr * NTHR + t] = make_float2(lm[2 * pr], lm[2 * pr + 1]);
        __syncthreads();
        float2 m = make_float2(-3.4e38f, -3.4e38f);
        for (int i = lane; i < NTHR; i += 32) {
            float2 v = part2[w * NTHR + i];
            m.x = fmaxf(m.x, v.x); m.y = fmaxf(m.y, v.y);
        }
        #pragma unroll
        for (int o = 16; o; o >>= 1) {
            m.x = fmaxf(m.x, __shfl_xor_sync(~0u, m.x, o));
            m.y = fmaxf(m.y, __shfl_xor_sync(~0u, m.y, o));
        }
        if (lane == 0) { s_rmax[2 * w] = m.x; s_rmax[2 * w + 1] = m.y; }
        if (t == 0) s_shift = 0.0f;
        __syncthreads();
        #pragma unroll
        for (int r = 0; r < ROWS; r++) {
            float rm = s_rmax[r];
            #pragma unroll
            for (int q = 0; q < 8; q++)
                E[r][q] = __expf(E[r][q] - rm);
        }
    }
    const float2 myrmax = make_float2(s_rmax[2 * w], s_rmax[2 * w + 1]);

    // emit prefetch for step 0 (lane0 of warp w owns rows 2w, 2w+1)
    float2 emit = make_float2(0.f, 0.f);
    if (lane == 0) emit = __ldg((const float2*)(h + row0 + 2 * w));
    __syncthreads();

    // ---- main sequential scan ----
    for (int s = 0; s < S; s++) {
        const float shift = s_shift;          // per-CTA shift; cancels exactly
        const float* fvr = g_fv[s & 1];

        // prefetch next step's emissions
        float2 emitN = emit;
        if (lane == 0 && s + 1 < S)
            emitN = __ldg((const float2*)(h + (size_t)(s + 1) * TAGS + row0 + 2 * w));

        // p = exp(fv - shift), own 8 entries, L1-bypassing (written by peer SMs)
        float4 f0 = __ldcg((const float4*)(fvr + c0));
        float4 f1 = __ldcg((const float4*)(fvr + c0) + 1);
        float p[8];
        p[0] = __expf(f0.x - shift); p[1] = __expf(f0.y - shift);
        p[2] = __expf(f0.z - shift); p[3] = __expf(f0.w - shift);
        p[4] = __expf(f1.x - shift); p[5] = __expf(f1.y - shift);
        p[6] = __expf(f1.z - shift); p[7] = __expf(f1.w - shift);

        // register GEMV: 16 rows x 8 cols, scalar FFMA
        float sv[ROWS];
        #pragma unroll
        for (int r = 0; r < ROWS; r++) {
            float a0 = E[r][0] * p[0];
            float a1 = E[r][1] * p[1];
            a0 = fmaf(E[r][2], p[2], a0);
            a1 = fmaf(E[r][3], p[3], a1);
            a0 = fmaf(E[r][4], p[4], a0);
            a1 = fmaf(E[r][5], p[5], a1);
            a0 = fmaf(E[r][6], p[6], a0);
            a1 = fmaf(E[r][7], p[7], a1);
            sv[r] = a0 + a1;
        }
        #pragma unroll
        for (int pr = 0; pr < 8; pr++)
            part2[pr * NTHR + t] = make_float2(sv[2 * pr], sv[2 * pr + 1]);
        __syncthreads();                                   // #1

        // warp w reduces row pair (2w, 2w+1) over all 256 thread-partials
        float2 acc = make_float2(0.f, 0.f);
        #pragma unroll
        for (int i = 0; i < NTHR / 32; i++) {
            float2 v = part2[w * NTHR + lane + 32 * i];
            acc.x += v.x; acc.y += v.y;
        }
        #pragma unroll
        for (int o = 16; o; o >>= 1) {
            acc.x += __shfl_xor_sync(~0u, acc.x, o);
            acc.y += __shfl_xor_sync(~0u, acc.y, o);
        }
        if (lane == 0) {
            float2 nf;
            nf.x = __logf(acc.x) + shift + myrmax.x + emit.x;
            nf.y = __logf(acc.y) + shift + myrmax.y + emit.y;
            *(float2*)(g_fv[(s + 1) & 1] + row0 + 2 * w) = nf;
            __threadfence();              // release fv before barrier arrive
        }
        emit = emitN;
        __syncthreads();                                   // #2
        if (t == 0) {
            if (w == 0) { }               // (t==0 is lane0/w0; s_shift below)
            s_shift = ( *(volatile float*)(g_fv[(s + 1) & 1] + row0 + 1) );
            atomicAdd(&g_bar, 1u);
            const unsigned target = (unsigned)(s + 1) * nb;
            while (*((volatile unsigned*)&g_bar) < target) { }
            __threadfence();              // acquire before next step's fv reads
        }
        __syncthreads();                                   // #3
    }

    // ---- final: logsumexp(fv + trans[END=1, :]) on CTA 0 ----
    if (b == 0) {
        const float* fvf  = g_fv[S & 1];
        const float* trow = trans + TAGS;         // row END_IDX = 1
        float* sp = (float*)part2;                // 16 KB scratch >= 8 KB needed
        float lm = -3.4e38f;
        #pragma unroll
        for (int k = 0; k < TAGS / NTHR; k++) {
            int j = t + NTHR * k;
            float v = __ldcg(fvf + j) + __ldg(trow + j);
            sp[j] = v;
            lm = fmaxf(lm, v);
        }
        #pragma unroll
        for (int o = 16; o; o >>= 1) lm = fmaxf(lm, __shfl_xor_sync(~0u, lm, o));
        if (lane == 0) s_rmax[w] = lm;
        __syncthreads();
        float M = s_rmax[0];
        #pragma unroll
        for (int q = 1; q < 8; q++) M = fmaxf(M, s_rmax[q]);
        float sum = 0.f;
        #pragma unroll
        for (int k = 0; k < TAGS / NTHR; k++)
            sum += __expf(sp[t + NTHR * k] - M);
        #pragma unroll
        for (int o = 16; o; o >>= 1) sum += __shfl_xor_sync(~0u, sum, o);
        __syncthreads();
        if (lane == 0) s_rmax[w] = sum;
        __syncthreads();
        if (t == 0) {
            float tot = 0.f;
            #pragma unroll
            for (int q = 0; q < 8; q++) tot += s_rmax[q];
            out[0] = __logf(tot) + M;
        }
    }
}

// ---------------- launch ----------------------------------------------------
extern "C" void kernel_launch(void* const* d_in, const int* in_sizes, int n_in,
                              void* d_out, int out_size) {
    const float* h     = (const float*)d_in[0];
    const float* trans = (const float*)d_in[1];
    float* out = (float*)d_out;
    const int S = in_sizes[0] / TAGS;

    init_kernel<<<(TAGS + 255) / 256, 256>>>();
    crf_main<<<NCTA, NTHR>>>(h, trans, out, S);
}